// round 13
// baseline (speedup 1.0000x reference)
#include <cuda_runtime.h>
#include <cuda_bf16.h>

#define TOK    9216
#define NTOT   288
#define LAT    256
#define DIN    512
#define NE     8
#define HID    128
#define OUTD   16384
#define BMOFF  75497472
#define AUXOFF 150994944
#define CS_STR 131
#define BSTR   72
#define MAXT   120

typedef unsigned long long ull;
typedef unsigned int u32;

// ---------------- device scratch ----------------
__device__ __align__(16) __nv_bfloat16 g_hh[2 * TOK * HID];
__device__ __align__(16) __nv_bfloat16 g_hl[2 * TOK * HID];
__device__ __align__(16) __nv_bfloat16 g_w2h[NE * OUTD * HID];
__device__ __align__(16) __nv_bfloat16 g_w2l[NE * OUTD * HID];
__device__ int   g_list[2][NE][TOK];
__device__ int   g_cnt[2][NE];
__device__ int   g_plist[64][TOK];    // token | (sa<<14), bucketed by pair a*8+b
__device__ int   g_pcnt[64];
__device__ int   g_tiles[MAXT];
__device__ float g_tokG[2 * TOK];
__device__ float g_psum[96][NE];
__device__ float g_lsum[96][NE];

__device__ __forceinline__ u32 s2u(const void* p) {
    u32 a; asm("{ .reg .u64 t; cvta.to.shared.u64 t, %1; cvt.u32.u64 %0, t; }" : "=r"(a) : "l"(p)); return a;
}
#define LDSM4(f, a) asm volatile("ldmatrix.sync.aligned.m8n8.x4.shared.b16 {%0,%1,%2,%3}, [%4];" \
    : "=r"((f)[0]), "=r"((f)[1]), "=r"((f)[2]), "=r"((f)[3]) : "r"(a))
#define LDSM2(f, a) asm volatile("ldmatrix.sync.aligned.m8n8.x2.shared.b16 {%0,%1}, [%2];" \
    : "=r"((f)[0]), "=r"((f)[1]) : "r"(a))
#define MMA(d, A, Bf) asm volatile( \
    "mma.sync.aligned.m16n8k16.row.col.f32.bf16.bf16.f32 {%0,%1,%2,%3},{%4,%5,%6,%7},{%8,%9},{%0,%1,%2,%3};" \
    : "+f"((d)[0]), "+f"((d)[1]), "+f"((d)[2]), "+f"((d)[3]) \
    : "r"((A)[0]), "r"((A)[1]), "r"((A)[2]), "r"((A)[3]), "r"((Bf)[0]), "r"((Bf)[1]))

__device__ __forceinline__ u32 hi2(float a, float b) {
    return (u32)__bfloat16_as_ushort(__float2bfloat16(a)) | ((u32)__bfloat16_as_ushort(__float2bfloat16(b)) << 16);
}
__device__ __forceinline__ u32 lo2(float a, float b) {
    float ra = a - __bfloat162float(__float2bfloat16(a));
    float rb = b - __bfloat162float(__float2bfloat16(b));
    return hi2(ra, rb);
}

// ---------------- K0 ----------------
__global__ void k_zero() {
    int i = threadIdx.x;
    if (i < 16) ((int*)g_cnt)[i] = 0;
    if (i < 64) g_pcnt[i] = 0;
}

// ---------------- K1: routing (512 thr: 16 warps x 6 tokens) ----------------
__global__ void __launch_bounds__(512) k_route(const float* __restrict__ z, const float* __restrict__ emb,
                                               const float* __restrict__ Wr, const float* __restrict__ br) {
    int blk = blockIdx.x, b = blk / 3, s = blk - b * 3;
    int warp = threadIdx.x >> 5, lane = threadIdx.x & 31;
    float accP = 0.f, accL = 0.f;
    for (int it = 0; it < 6; it++) {
        int n = s * 96 + warp * 6 + it;
        int t = b * NTOT + n;
        float lg[8];
#pragma unroll
        for (int e = 0; e < 8; e++) lg[e] = 0.f;
        const float* zr = z + (size_t)t * LAT;
        const float* er = emb + (size_t)n * LAT;
        for (int i = lane; i < DIN; i += 32) {
            float xv = (i < LAT) ? zr[i] : er[i - LAT];
            const float4 w0 = *(const float4*)(Wr + i * 8);
            const float4 w1 = *(const float4*)(Wr + i * 8 + 4);
            lg[0] += xv * w0.x; lg[1] += xv * w0.y; lg[2] += xv * w0.z; lg[3] += xv * w0.w;
            lg[4] += xv * w1.x; lg[5] += xv * w1.y; lg[6] += xv * w1.z; lg[7] += xv * w1.w;
        }
#pragma unroll
        for (int off = 16; off > 0; off >>= 1)
#pragma unroll
            for (int e = 0; e < 8; e++) lg[e] += __shfl_xor_sync(0xffffffffu, lg[e], off);
#pragma unroll
        for (int e = 0; e < 8; e++) lg[e] = (lg[e] + br[e]) * (1.0f / 1.5f);
        int e0 = 0; float v0 = lg[0];
#pragma unroll
        for (int e = 1; e < 8; e++) if (lg[e] > v0) { v0 = lg[e]; e0 = e; }
        int e1 = -1; float v1 = -3.4e38f;
#pragma unroll
        for (int e = 0; e < 8; e++) if (e != e0 && lg[e] > v1) { v1 = lg[e]; e1 = e; }
        float ex = __expf(v1 - v0);
        float g0 = 1.f / (1.f + ex), g1 = ex * g0;
        float den = 0.f, pr[8];
#pragma unroll
        for (int e = 0; e < 8; e++) { pr[e] = __expf(lg[e] - v0); den += pr[e]; }
        float rden = 1.f / den;
        if (lane < 8) {
            accP += pr[lane] * rden;
            accL += (lane == e0 ? g0 : 0.f) + (lane == e1 ? g1 : 0.f);
        }
        if (lane == 0) {
            g_tokG[t] = g0; g_tokG[TOK + t] = g1;
            int p0 = atomicAdd(&g_cnt[0][e0], 1); g_list[0][e0][p0] = t;
            int p1 = atomicAdd(&g_cnt[1][e1], 1); g_list[1][e1][p1] = t;
            int a = min(e0, e1), bb = max(e0, e1);
            int sa = (e0 < e1) ? 0 : 1;                 // slot holding expert a
            int pp = a * 8 + bb;
            int pos = atomicAdd(&g_pcnt[pp], 1);
            g_plist[pp][pos] = t | (sa << 14);
        }
    }
    __shared__ float sP[16][8], sL[16][8];
    if (lane < 8) { sP[warp][lane] = accP; sL[warp][lane] = accL; }
    __syncthreads();
    if (threadIdx.x < 8) {
        float p = 0.f, l = 0.f;
        for (int w = 0; w < 16; w++) { p += sP[w][threadIdx.x]; l += sL[w][threadIdx.x]; }
        g_psum[blk][threadIdx.x] = p; g_lsum[blk][threadIdx.x] = l;
    }
}

// ---------------- K2: merged prep kernel.
// blocks [0,1024): W2 transform (nt = bx&127, e = bx>>7); block 0 thread 255 also
// builds the pair tile schedule. blocks [1024, 1024+2304): hidden GEMM.
__global__ void __launch_bounds__(256) k_prep(const float* __restrict__ W2,
                                              const float* __restrict__ z,
                                              const float* __restrict__ emb,
                                              const float* __restrict__ W1,
                                              const float* __restrict__ b1) {
    int bx = blockIdx.x;
    int tid = threadIdx.x;
    if (bx < 1024) {
        // ---------- W2 -> permuted K-major bf16 hi/lo ----------
        __shared__ float s[64][132];
        int nt = bx & 127, e = bx >> 7;
        if (bx == 0 && tid == 255) {       // fold k_sched onto an idle thread
            int idx = 0;
            for (int p = 0; p < 64; p++) {
                int c = g_pcnt[p];
                int ntt = (c + 127) >> 7;
                for (int m = 0; m < ntt && idx < MAXT; m++) g_tiles[idx++] = (p << 8) | m;
            }
            while (idx < MAXT) g_tiles[idx++] = -1;
        }
        for (int kp = 0; kp < 2; kp++) {
            if (tid < 128) {
                for (int task = tid; task < 1024; task += 128) {
                    int k = task >> 4, r = task & 15;
                    const float* src = W2 + ((size_t)(e * 128 + kp * 64 + k)) * OUTD + r * 1024 + nt * 8;
                    float4 v0 = *(const float4*)src, v1 = *(const float4*)(src + 4);
                    float* d = &s[k][r * 8];
                    *(float4*)d = v0; *(float4*)(d + 4) = v1;
                }
            }
            __syncthreads();
            if (tid < 128) {
                int j = tid;
                size_t base = ((size_t)(e * OUTD + nt * 128 + j)) * HID + kp * 64;
#pragma unroll
                for (int c = 0; c < 8; c++) {
                    u32 wh[4], wl[4];
#pragma unroll
                    for (int p = 0; p < 4; p++) {
                        float a = s[c * 8 + p * 2][j], b = s[c * 8 + p * 2 + 1][j];
                        wh[p] = hi2(a, b); wl[p] = lo2(a, b);
                    }
                    *(uint4*)&g_w2h[base + c * 8] = make_uint4(wh[0], wh[1], wh[2], wh[3]);
                    *(uint4*)&g_w2l[base + c * 8] = make_uint4(wl[0], wl[1], wl[2], wl[3]);
                }
            }
            __syncthreads();
        }
        return;
    }
    // ---------- hidden GEMM + silu + gate -> bf16 hi/lo ----------
    {
        int idx = bx - 1024;                    // 0..2303
        int slot = idx / 1152;
        int rem = idx - slot * 1152;
        int e = rem / 144;
        int m0 = (rem - e * 144) * 64;
        int cnt = g_cnt[slot][e];
        if (m0 >= cnt) return;
        int rows = min(64, cnt - m0);
        __shared__ __align__(16) float Xs[16][64];
        __shared__ __align__(16) float Ws[16][128];
        __shared__ int stok[64];
        __shared__ float sg[64];
        if (tid < 64) {
            int t = (tid < rows) ? g_list[slot][e][m0 + tid] : -1;
            stok[tid] = t;
            sg[tid] = (t >= 0) ? g_tokG[slot * TOK + t] : 0.f;
        }
        __syncthreads();
        int tx = tid & 15, ty = tid >> 4, j0 = tx * 8, mr = ty * 4;
        float acc[4][8];
#pragma unroll
        for (int a = 0; a < 4; a++)
#pragma unroll
            for (int j = 0; j < 8; j++) acc[a][j] = 0.f;
        const float* W1e = W1 + (size_t)e * DIN * HID;
        int lm = tid >> 2, lq = (tid & 3) * 4, lk = tid >> 4, ln = (tid & 15) * 8;
        for (int k0 = 0; k0 < DIN; k0 += 16) {
            float4 v = make_float4(0.f, 0.f, 0.f, 0.f);
            int t = stok[lm];
            if (t >= 0) {
                int kk = k0 + lq;
                if (kk < LAT) v = *(const float4*)(z + (size_t)t * LAT + kk);
                else          v = *(const float4*)(emb + (size_t)(t % NTOT) * LAT + (kk - LAT));
            }
            const float* src = W1e + (size_t)(k0 + lk) * HID + ln;
            float4 w0 = *(const float4*)src, w1 = *(const float4*)(src + 4);
            __syncthreads();
            Xs[lq][lm] = v.x; Xs[lq + 1][lm] = v.y; Xs[lq + 2][lm] = v.z; Xs[lq + 3][lm] = v.w;
            *(float4*)&Ws[lk][ln] = w0; *(float4*)&Ws[lk][ln + 4] = w1;
            __syncthreads();
#pragma unroll
            for (int kk = 0; kk < 16; kk++) {
                float4 a = *(const float4*)&Xs[kk][mr];
                float4 b0 = *(const float4*)&Ws[kk][j0];
                float4 b1v = *(const float4*)&Ws[kk][j0 + 4];
                float av[4] = {a.x, a.y, a.z, a.w};
                float bv[8] = {b0.x, b0.y, b0.z, b0.w, b1v.x, b1v.y, b1v.z, b1v.w};
#pragma unroll
                for (int mm = 0; mm < 4; mm++)
#pragma unroll
                    for (int jj = 0; jj < 8; jj++)
                        acc[mm][jj] = fmaf(av[mm], bv[jj], acc[mm][jj]);
            }
        }
        const float* b1e = b1 + e * HID;
#pragma unroll
        for (int mm = 0; mm < 4; mm++) {
            int m = mr + mm, t = stok[m];
            if (t < 0) continue;
            float g = sg[m], o[8];
#pragma unroll
            for (int jj = 0; jj < 8; jj++) {
                float c = acc[mm][jj] + b1e[j0 + jj];
                o[jj] = c * g / (1.f + __expf(-c));
            }
            size_t base = ((size_t)(slot * TOK + t)) * HID + j0;
            *(uint4*)&g_hh[base] = make_uint4(hi2(o[0], o[1]), hi2(o[2], o[3]), hi2(o[4], o[5]), hi2(o[6], o[7]));
            *(uint4*)&g_hl[base] = make_uint4(lo2(o[0], o[1]), lo2(o[2], o[3]), lo2(o[4], o[5]), lo2(o[6], o[7]));
        }
    }
}

// ---------------- K3: pair-fused output GEMM (R11-proven). M=128 x N=128, K=2x128.
__global__ void __launch_bounds__(256, 2) k_out_pair(const float* __restrict__ b2,
                                                     float* __restrict__ out) {
    int ti = g_tiles[blockIdx.x];
    if (ti < 0) return;
    int pp = ti >> 8, ea = pp >> 3, eb = pp & 7;
    int m0 = (ti & 255) * 128;
    int rows = min(128, g_pcnt[pp] - m0);
    int nt = blockIdx.y, h0 = nt * 8;

    extern __shared__ __align__(16) __nv_bfloat16 sm[];
    u32 smb = s2u(sm);
    __nv_bfloat16* sAh = sm;
    __nv_bfloat16* sAl = sm + 128 * BSTR;
    __nv_bfloat16* sBh = sm + 2 * 128 * BSTR;
    __nv_bfloat16* sBl = sm + 3 * 128 * BSTR;
    __shared__ int   sbase[128];
    __shared__ int   srcrow[128];
    __shared__ float sga[128], sgb[128];

    int tid = threadIdx.x, wid = tid >> 5, lane = tid & 31;
    int wm = wid >> 2, wn = wid & 3;

    if (tid < 128) {
        int base = -1, sr = 0; float ga = 0.f, gb = 0.f;
        if (tid < rows) {
            int tt = g_plist[pp][m0 + tid];
            int t = tt & 16383, sa = (tt >> 14) & 1;
            ga = g_tokG[sa * TOK + t];
            gb = g_tokG[(1 - sa) * TOK + t];
            sr = sa * TOK + t;
            int b = t / NTOT, n = t - b * NTOT;
            int s = n / 96, rem = n - s * 96, l = rem >> 2, jt = rem & 3;
            int chunk = ((b * 3 + s) * 24 + l) * 2 + (jt >> 1);
            base = chunk * OUTD + (jt & 1);
        }
        sbase[tid] = base; srcrow[tid] = sr; sga[tid] = ga; sgb[tid] = gb;
    }
    __syncthreads();

    float acc[4][4][4];
#pragma unroll
    for (int i = 0; i < 4; i++)
#pragma unroll
        for (int j = 0; j < 4; j++)
#pragma unroll
            for (int p = 0; p < 4; p++) acc[i][j][p] = 0.f;

    u32 aRow = wm * 64 + (lane & 7) + ((lane >> 3) & 1) * 8;
    u32 aKof = (lane >> 4) * 8;
    int ll = lane & 15;
    u32 bRow = wn * 32 + (ll & 7);
    u32 bKof = ((ll >> 3) & 1) * 8;
    u32 aAddrH = smb + (aRow * BSTR + aKof) * 2;
    u32 aAddrL = aAddrH + 128 * BSTR * 2;
    u32 bAddrH = smb + 2 * 128 * BSTR * 2 + (bRow * BSTR + bKof) * 2;
    u32 bAddrL = bAddrH + 128 * BSTR * 2;

    int lr = tid >> 1, half = tid & 1;
    bool valid = lr < rows;
    int sra = valid ? srcrow[lr] : 0;

    for (int ch = 0; ch < 4; ch++) {          // {expert a, expert b} x {kc0, kc1}
        int ph = ch >> 1, kc = ch & 1;
        int e = ph ? eb : ea;
        int rowidx = sra;
        if (ph) rowidx = (sra >= TOK) ? (sra - TOK) : (sra + TOK);
        {
            size_t aoff = ((size_t)rowidx) * HID + kc * 64 + half * 32;
            const uint4* ah = (const uint4*)(g_hh + aoff);
            const uint4* al = (const uint4*)(g_hl + aoff);
            uint4 z4 = make_uint4(0, 0, 0, 0);
            uint4* dh = (uint4*)(sAh + lr * BSTR + half * 32);
            uint4* dl = (uint4*)(sAl + lr * BSTR + half * 32);
#pragma unroll
            for (int q = 0; q < 4; q++) {
                dh[q] = valid ? ah[q] : z4;
                dl[q] = valid ? al[q] : z4;
            }
            size_t boff = ((size_t)(e * OUTD + nt * 128 + lr)) * HID + kc * 64 + half * 32;
            const uint4* bh = (const uint4*)(g_w2h + boff);
            const uint4* bl = (const uint4*)(g_w2l + boff);
            uint4* eh = (uint4*)(sBh + lr * BSTR + half * 32);
            uint4* el = (uint4*)(sBl + lr * BSTR + half * 32);
#pragma unroll
            for (int q = 0; q < 4; q++) { eh[q] = bh[q]; el[q] = bl[q]; }
        }
        __syncthreads();
#pragma unroll
        for (int ks = 0; ks < 4; ks++) {
            u32 koff = (ks * 16) * 2;
            u32 af[4][4], bhf[4][2], blf[4][2];
#pragma unroll
            for (int mt = 0; mt < 4; mt++) LDSM4(af[mt], aAddrH + mt * 16 * BSTR * 2 + koff);
#pragma unroll
            for (int nn = 0; nn < 4; nn++) {
                LDSM2(bhf[nn], bAddrH + nn * 8 * BSTR * 2 + koff);
                LDSM2(blf[nn], bAddrL + nn * 8 * BSTR * 2 + koff);
            }
#pragma unroll
            for (int mt = 0; mt < 4; mt++)
#pragma unroll
                for (int nn = 0; nn < 4; nn++) {
                    MMA(acc[mt][nn], af[mt], bhf[nn]);
                    MMA(acc[mt][nn], af[mt], blf[nn]);
                }
#pragma unroll
            for (int mt = 0; mt < 4; mt++) LDSM4(af[mt], aAddrL + mt * 16 * BSTR * 2 + koff);
#pragma unroll
            for (int mt = 0; mt < 4; mt++)
#pragma unroll
                for (int nn = 0; nn < 4; nn++)
                    MMA(acc[mt][nn], af[mt], bhf[nn]);
        }
        __syncthreads();
    }

    float* Cs = (float*)sm;
#pragma unroll
    for (int mt = 0; mt < 4; mt++)
#pragma unroll
        for (int nn = 0; nn < 4; nn++) {
            int row = wm * 64 + mt * 16 + (lane >> 2);
            int col = wn * 32 + nn * 8 + (lane & 3) * 2;
            Cs[col * CS_STR + row]           = acc[mt][nn][0];
            Cs[(col + 1) * CS_STR + row]     = acc[mt][nn][1];
            Cs[col * CS_STR + row + 8]       = acc[mt][nn][2];
            Cs[(col + 1) * CS_STR + row + 8] = acc[mt][nn][3];
        }
    __syncthreads();

    const float* ba = b2 + ea * OUTD;
    const float* bb = b2 + eb * OUTD;
    int q = tid & 31, rowgrp = tid >> 5;
    int rA = q >> 1, h4A = (q & 1) * 4;
    int aoffA = rA * 1024 + h0 + h4A;
    int jA = rA * 8 + h4A;
    float bAa[4], bAb[4];
#pragma unroll
    for (int u = 0; u < 4; u++) { bAa[u] = ba[aoffA + u]; bAb[u] = bb[aoffA + u]; }
    int hB = q >> 2, rB4 = (q & 3) * 4;
    int aoffB = h0 * 16 + q * 4;
    int jB[4]; float bBa[4], bBb[4];
#pragma unroll
    for (int u = 0; u < 4; u++) {
        jB[u] = (rB4 + u) * 8 + hB;
        bBa[u] = ba[(rB4 + u) * 1024 + h0 + hB];
        bBb[u] = bb[(rB4 + u) * 1024 + h0 + hB];
    }

#pragma unroll 2
    for (int it = 0; it < 16; it++) {
        int m = it * 8 + rowgrp;
        int bs = sbase[m];
        if (bs < 0) continue;
        float ga = sga[m], gb = sgb[m];
        float4 v; size_t addr;
        if (bs & 1) {
            v.x = Cs[jB[0] * CS_STR + m] + ga * bBa[0] + gb * bBb[0];
            v.y = Cs[jB[1] * CS_STR + m] + ga * bBa[1] + gb * bBb[1];
            v.z = Cs[jB[2] * CS_STR + m] + ga * bBa[2] + gb * bBb[2];
            v.w = Cs[jB[3] * CS_STR + m] + ga * bBa[3] + gb * bBb[3];
            addr = (size_t)BMOFF + (size_t)(bs & ~1) + aoffB;
        } else {
            v.x = Cs[(jA + 0) * CS_STR + m] + ga * bAa[0] + gb * bAb[0];
            v.y = Cs[(jA + 1) * CS_STR + m] + ga * bAa[1] + gb * bAb[1];
            v.z = Cs[(jA + 2) * CS_STR + m] + ga * bAa[2] + gb * bAb[2];
            v.w = Cs[(jA + 3) * CS_STR + m] + ga * bAa[3] + gb * bAb[3];
            addr = (size_t)bs + aoffA;
        }
        *(float4*)(out + addr) = v;
    }
}

// ---------------- K4: aux ----------------
__global__ void k_aux(float* __restrict__ out) {
    if (threadIdx.x == 0 && blockIdx.x == 0) {
        double aux = 0.0;
        for (int s = 0; s < 3; s++) {
            double dot = 0.0;
            for (int e = 0; e < NE; e++) {
                double P = 0.0, L = 0.0;
                for (int b = 0; b < 32; b++) {
                    P += (double)g_psum[b * 3 + s][e];
                    L += (double)g_lsum[b * 3 + s][e];
                }
                dot += P * L;
            }
            double a = 8.0 * dot / (3072.0 * 3072.0) - 1.0;
            if (a > 0.0) aux += a;
        }
        out[AUXOFF] = (float)aux;
    }
}

extern "C" void kernel_launch(void* const* d_in, const int* in_sizes, int n_in,
                              void* d_out, int out_size) {
    const float* z   = (const float*)d_in[0];
    const float* emb = (const float*)d_in[1];
    const float* Wr  = (const float*)d_in[2];
    const float* br  = (const float*)d_in[3];
    const float* W1  = (const float*)d_in[4];
    const float* b1  = (const float*)d_in[5];
    const float* W2  = (const float*)d_in[6];
    const float* b2  = (const float*)d_in[7];
    float* out = (float*)d_out;
    (void)in_sizes; (void)n_in; (void)out_size;

    int smem = 4 * 128 * BSTR * 2;   // 73728 B
    cudaFuncSetAttribute(k_out_pair, cudaFuncAttributeMaxDynamicSharedMemorySize, smem);

    k_zero<<<1, 64>>>();
    k_route<<<96, 512>>>(z, emb, Wr, br);
    k_prep<<<1024 + 2304, 256>>>(W2, z, emb, W1, b1);
    k_out_pair<<<dim3(MAXT, 128), 256, smem>>>(b2, out);
    k_aux<<<1, 32>>>(out);
}

// round 14
// speedup vs baseline: 1.5359x; 1.5359x over previous
#include <cuda_runtime.h>
#include <cuda_bf16.h>

#define TOK    9216
#define NTOT   288
#define LAT    256
#define DIN    512
#define NE     8
#define HID    128
#define OUTD   16384
#define BMOFF  75497472
#define AUXOFF 150994944
#define CS_STR 131
#define BSTR   72
#define MAXT   120

typedef unsigned long long ull;
typedef unsigned int u32;

// ---------------- device scratch ----------------
__device__ __align__(16) __nv_bfloat16 g_hh[2 * TOK * HID];
__device__ __align__(16) __nv_bfloat16 g_hl[2 * TOK * HID];
__device__ __align__(16) __nv_bfloat16 g_w2h[NE * OUTD * HID];
__device__ __align__(16) __nv_bfloat16 g_w2l[NE * OUTD * HID];
__device__ int   g_list[2][NE][TOK];
__device__ int   g_cnt[2][NE];
__device__ int   g_plist[64][TOK];    // token | (sa<<14), bucketed by pair a*8+b
__device__ int   g_pcnt[64];
__device__ float g_tokG[2 * TOK];
__device__ float g_psum[96][NE];
__device__ float g_lsum[96][NE];

__device__ __forceinline__ u32 s2u(const void* p) {
    u32 a; asm("{ .reg .u64 t; cvta.to.shared.u64 t, %1; cvt.u32.u64 %0, t; }" : "=r"(a) : "l"(p)); return a;
}
#define LDSM4(f, a) asm volatile("ldmatrix.sync.aligned.m8n8.x4.shared.b16 {%0,%1,%2,%3}, [%4];" \
    : "=r"((f)[0]), "=r"((f)[1]), "=r"((f)[2]), "=r"((f)[3]) : "r"(a))
#define LDSM2(f, a) asm volatile("ldmatrix.sync.aligned.m8n8.x2.shared.b16 {%0,%1}, [%2];" \
    : "=r"((f)[0]), "=r"((f)[1]) : "r"(a))
#define MMA(d, A, Bf) asm volatile( \
    "mma.sync.aligned.m16n8k16.row.col.f32.bf16.bf16.f32 {%0,%1,%2,%3},{%4,%5,%6,%7},{%8,%9},{%0,%1,%2,%3};" \
    : "+f"((d)[0]), "+f"((d)[1]), "+f"((d)[2]), "+f"((d)[3]) \
    : "r"((A)[0]), "r"((A)[1]), "r"((A)[2]), "r"((A)[3]), "r"((Bf)[0]), "r"((Bf)[1]))
#define CP_COMMIT() asm volatile("cp.async.commit_group;" ::: "memory")
#define CP_WAIT0()  asm volatile("cp.async.wait_group 0;" ::: "memory")

__device__ __forceinline__ void cp16(u32 d, const void* s) {
    asm volatile("cp.async.cg.shared.global [%0], [%1], 16;" :: "r"(d), "l"(s));
}
__device__ __forceinline__ void cp16z(u32 d, const void* s, int nb) {
    asm volatile("cp.async.cg.shared.global [%0], [%1], 16, %2;" :: "r"(d), "l"(s), "r"(nb));
}
__device__ __forceinline__ u32 hi2(float a, float b) {
    return (u32)__bfloat16_as_ushort(__float2bfloat16(a)) | ((u32)__bfloat16_as_ushort(__float2bfloat16(b)) << 16);
}
__device__ __forceinline__ u32 lo2(float a, float b) {
    float ra = a - __bfloat162float(__float2bfloat16(a));
    float rb = b - __bfloat162float(__float2bfloat16(b));
    return hi2(ra, rb);
}

// ---------------- K1: W2 transform (+ counter zeroing, runs before k_route) ----------------
__global__ void __launch_bounds__(128) k_w2t(const float* __restrict__ W2) {
    int nt = blockIdx.x, e = blockIdx.y;
    int tid = threadIdx.x;
    if (blockIdx.x == 0 && blockIdx.y == 0) {    // fold k_zero (ordered before k_route by stream)
        if (tid < 16) ((int*)g_cnt)[tid] = 0;
        if (tid < 64) g_pcnt[tid] = 0;
    }
    __shared__ float s[64][132];
    for (int kp = 0; kp < 2; kp++) {
        for (int task = tid; task < 1024; task += 128) {
            int k = task >> 4, r = task & 15;
            const float* src = W2 + ((size_t)(e * 128 + kp * 64 + k)) * OUTD + r * 1024 + nt * 8;
            float4 v0 = *(const float4*)src, v1 = *(const float4*)(src + 4);
            float* d = &s[k][r * 8];
            *(float4*)d = v0; *(float4*)(d + 4) = v1;
        }
        __syncthreads();
        int j = tid;
        size_t base = ((size_t)(e * OUTD + nt * 128 + j)) * HID + kp * 64;
#pragma unroll
        for (int c = 0; c < 8; c++) {
            u32 wh[4], wl[4];
#pragma unroll
            for (int p = 0; p < 4; p++) {
                float a = s[c * 8 + p * 2][j], b = s[c * 8 + p * 2 + 1][j];
                wh[p] = hi2(a, b); wl[p] = lo2(a, b);
            }
            *(uint4*)&g_w2h[base + c * 8] = make_uint4(wh[0], wh[1], wh[2], wh[3]);
            *(uint4*)&g_w2l[base + c * 8] = make_uint4(wl[0], wl[1], wl[2], wl[3]);
        }
        __syncthreads();
    }
}

// ---------------- K2: routing (512 thr: 16 warps x 6 tokens) ----------------
__global__ void __launch_bounds__(512) k_route(const float* __restrict__ z, const float* __restrict__ emb,
                                               const float* __restrict__ Wr, const float* __restrict__ br) {
    int blk = blockIdx.x, b = blk / 3, s = blk - b * 3;
    int warp = threadIdx.x >> 5, lane = threadIdx.x & 31;
    float accP = 0.f, accL = 0.f;
    for (int it = 0; it < 6; it++) {
        int n = s * 96 + warp * 6 + it;
        int t = b * NTOT + n;
        float lg[8];
#pragma unroll
        for (int e = 0; e < 8; e++) lg[e] = 0.f;
        const float* zr = z + (size_t)t * LAT;
        const float* er = emb + (size_t)n * LAT;
        for (int i = lane; i < DIN; i += 32) {
            float xv = (i < LAT) ? zr[i] : er[i - LAT];
            const float4 w0 = *(const float4*)(Wr + i * 8);
            const float4 w1 = *(const float4*)(Wr + i * 8 + 4);
            lg[0] += xv * w0.x; lg[1] += xv * w0.y; lg[2] += xv * w0.z; lg[3] += xv * w0.w;
            lg[4] += xv * w1.x; lg[5] += xv * w1.y; lg[6] += xv * w1.z; lg[7] += xv * w1.w;
        }
#pragma unroll
        for (int off = 16; off > 0; off >>= 1)
#pragma unroll
            for (int e = 0; e < 8; e++) lg[e] += __shfl_xor_sync(0xffffffffu, lg[e], off);
#pragma unroll
        for (int e = 0; e < 8; e++) lg[e] = (lg[e] + br[e]) * (1.0f / 1.5f);
        int e0 = 0; float v0 = lg[0];
#pragma unroll
        for (int e = 1; e < 8; e++) if (lg[e] > v0) { v0 = lg[e]; e0 = e; }
        int e1 = -1; float v1 = -3.4e38f;
#pragma unroll
        for (int e = 0; e < 8; e++) if (e != e0 && lg[e] > v1) { v1 = lg[e]; e1 = e; }
        float ex = __expf(v1 - v0);
        float g0 = 1.f / (1.f + ex), g1 = ex * g0;
        float den = 0.f, pr[8];
#pragma unroll
        for (int e = 0; e < 8; e++) { pr[e] = __expf(lg[e] - v0); den += pr[e]; }
        float rden = 1.f / den;
        if (lane < 8) {
            accP += pr[lane] * rden;
            accL += (lane == e0 ? g0 : 0.f) + (lane == e1 ? g1 : 0.f);
        }
        if (lane == 0) {
            g_tokG[t] = g0; g_tokG[TOK + t] = g1;
            int p0 = atomicAdd(&g_cnt[0][e0], 1); g_list[0][e0][p0] = t;
            int p1 = atomicAdd(&g_cnt[1][e1], 1); g_list[1][e1][p1] = t;
            int a = min(e0, e1), bb = max(e0, e1);
            int sa = (e0 < e1) ? 0 : 1;                 // slot holding expert a
            int pp = a * 8 + bb;
            int pos = atomicAdd(&g_pcnt[pp], 1);
            g_plist[pp][pos] = t | (sa << 14);
        }
    }
    __shared__ float sP[16][8], sL[16][8];
    if (lane < 8) { sP[warp][lane] = accP; sL[warp][lane] = accL; }
    __syncthreads();
    if (threadIdx.x < 8) {
        float p = 0.f, l = 0.f;
        for (int w = 0; w < 16; w++) { p += sP[w][threadIdx.x]; l += sL[w][threadIdx.x]; }
        g_psum[blk][threadIdx.x] = p; g_lsum[blk][threadIdx.x] = l;
    }
}

// ---------------- K3: hidden GEMM + silu + gate -> bf16 hi/lo ----------------
__global__ void __launch_bounds__(256) k_hidden(const float* __restrict__ z,
                                                const float* __restrict__ emb,
                                                const float* __restrict__ W1,
                                                const float* __restrict__ b1) {
    int slot = blockIdx.z, e = blockIdx.y;
    int cnt = g_cnt[slot][e];
    int m0 = blockIdx.x * 64;
    if (m0 >= cnt) return;
    int rows = min(64, cnt - m0);
    __shared__ __align__(16) float Xs[16][64];
    __shared__ __align__(16) float Ws[16][128];
    __shared__ int stok[64];
    __shared__ float sg[64];
    int tid = threadIdx.x;
    if (tid < 64) {
        int t = (tid < rows) ? g_list[slot][e][m0 + tid] : -1;
        stok[tid] = t;
        sg[tid] = (t >= 0) ? g_tokG[slot * TOK + t] : 0.f;
    }
    __syncthreads();
    int tx = tid & 15, ty = tid >> 4, j0 = tx * 8, mr = ty * 4;
    float acc[4][8];
#pragma unroll
    for (int a = 0; a < 4; a++)
#pragma unroll
        for (int j = 0; j < 8; j++) acc[a][j] = 0.f;
    const float* W1e = W1 + (size_t)e * DIN * HID;
    int lm = tid >> 2, lq = (tid & 3) * 4, lk = tid >> 4, ln = (tid & 15) * 8;
    for (int k0 = 0; k0 < DIN; k0 += 16) {
        float4 v = make_float4(0.f, 0.f, 0.f, 0.f);
        int t = stok[lm];
        if (t >= 0) {
            int kk = k0 + lq;
            if (kk < LAT) v = *(const float4*)(z + (size_t)t * LAT + kk);
            else          v = *(const float4*)(emb + (size_t)(t % NTOT) * LAT + (kk - LAT));
        }
        const float* src = W1e + (size_t)(k0 + lk) * HID + ln;
        float4 w0 = *(const float4*)src, w1 = *(const float4*)(src + 4);
        __syncthreads();
        Xs[lq][lm] = v.x; Xs[lq + 1][lm] = v.y; Xs[lq + 2][lm] = v.z; Xs[lq + 3][lm] = v.w;
        *(float4*)&Ws[lk][ln] = w0; *(float4*)&Ws[lk][ln + 4] = w1;
        __syncthreads();
#pragma unroll
        for (int kk = 0; kk < 16; kk++) {
            float4 a = *(const float4*)&Xs[kk][mr];
            float4 b0 = *(const float4*)&Ws[kk][j0];
            float4 b1v = *(const float4*)&Ws[kk][j0 + 4];
            float av[4] = {a.x, a.y, a.z, a.w};
            float bv[8] = {b0.x, b0.y, b0.z, b0.w, b1v.x, b1v.y, b1v.z, b1v.w};
#pragma unroll
            for (int mm = 0; mm < 4; mm++)
#pragma unroll
                for (int jj = 0; jj < 8; jj++)
                    acc[mm][jj] = fmaf(av[mm], bv[jj], acc[mm][jj]);
        }
    }
    const float* b1e = b1 + e * HID;
#pragma unroll
    for (int mm = 0; mm < 4; mm++) {
        int m = mr + mm, t = stok[m];
        if (t < 0) continue;
        float g = sg[m], o[8];
#pragma unroll
        for (int jj = 0; jj < 8; jj++) {
            float c = acc[mm][jj] + b1e[j0 + jj];
            o[jj] = c * g / (1.f + __expf(-c));
        }
        size_t base = ((size_t)(slot * TOK + t)) * HID + j0;
        *(uint4*)&g_hh[base] = make_uint4(hi2(o[0], o[1]), hi2(o[2], o[3]), hi2(o[4], o[5]), hi2(o[6], o[7]));
        *(uint4*)&g_hl[base] = make_uint4(lo2(o[0], o[1]), lo2(o[2], o[3]), lo2(o[4], o[5]), lo2(o[6], o[7]));
    }
}

// ---------------- K4: pair-fused output GEMM (R11 structure, cp.async.cg fills,
// self-computed tile schedule). M=128 x N=128, K=2x128 over {ea,eb}.
__global__ void __launch_bounds__(256, 2) k_out_pair(const float* __restrict__ b2,
                                                     float* __restrict__ out) {
    __shared__ int stile;
    int tid = threadIdx.x;
    if (tid == 0) {
        int want = blockIdx.x, idx = 0, res = -1;
        for (int p = 0; p < 64; p++) {
            int nt = (g_pcnt[p] + 127) >> 7;
            if (want < idx + nt) { res = (p << 8) | (want - idx); break; }
            idx += nt;
        }
        stile = res;
    }
    __syncthreads();
    int ti = stile;
    if (ti < 0) return;
    int pp = ti >> 8, ea = pp >> 3, eb = pp & 7;
    int m0 = (ti & 255) * 128;
    int rows = min(128, g_pcnt[pp] - m0);
    int nt = blockIdx.y, h0 = nt * 8;

    extern __shared__ __align__(16) __nv_bfloat16 sm[];
    u32 smb = s2u(sm);
    u32 sAh = smb;
    u32 sAl = smb + 128 * BSTR * 2;
    u32 sBh = smb + 2 * 128 * BSTR * 2;
    u32 sBl = smb + 3 * 128 * BSTR * 2;
    __shared__ int   sbase[128];
    __shared__ int   srcrow[128];
    __shared__ float sga[128], sgb[128];

    int wid = tid >> 5, lane = tid & 31;
    int wm = wid >> 2, wn = wid & 3;

    if (tid < 128) {
        int base = -1, sr = 0; float ga = 0.f, gb = 0.f;
        if (tid < rows) {
            int tt = g_plist[pp][m0 + tid];
            int t = tt & 16383, sa = (tt >> 14) & 1;
            ga = g_tokG[sa * TOK + t];
            gb = g_tokG[(1 - sa) * TOK + t];
            sr = sa * TOK + t;
            int b = t / NTOT, n = t - b * NTOT;
            int s = n / 96, rem = n - s * 96, l = rem >> 2, jt = rem & 3;
            int chunk = ((b * 3 + s) * 24 + l) * 2 + (jt >> 1);
            base = chunk * OUTD + (jt & 1);
        }
        sbase[tid] = base; srcrow[tid] = sr; sga[tid] = ga; sgb[tid] = gb;
    }
    __syncthreads();

    float acc[4][4][4];
#pragma unroll
    for (int i = 0; i < 4; i++)
#pragma unroll
        for (int j = 0; j < 4; j++)
#pragma unroll
            for (int p = 0; p < 4; p++) acc[i][j][p] = 0.f;

    u32 aRow = wm * 64 + (lane & 7) + ((lane >> 3) & 1) * 8;
    u32 aKof = (lane >> 4) * 8;
    int ll = lane & 15;
    u32 bRow = wn * 32 + (ll & 7);
    u32 bKof = ((ll >> 3) & 1) * 8;
    u32 aAddrH = smb + (aRow * BSTR + aKof) * 2;
    u32 aAddrL = aAddrH + 128 * BSTR * 2;
    u32 bAddrH = smb + 2 * 128 * BSTR * 2 + (bRow * BSTR + bKof) * 2;
    u32 bAddrL = bAddrH + 128 * BSTR * 2;

    int lr = tid >> 1, half = tid & 1;
    bool valid = lr < rows;
    int nbA = valid ? 16 : 0;
    int sra = valid ? srcrow[lr] : 0;
    u32 aDstH = sAh + (lr * BSTR + half * 32) * 2;
    u32 aDstL = sAl + (lr * BSTR + half * 32) * 2;
    u32 bDstH = sBh + (lr * BSTR + half * 32) * 2;
    u32 bDstL = sBl + (lr * BSTR + half * 32) * 2;

    for (int ch = 0; ch < 4; ch++) {          // {expert a, expert b} x {kc0, kc1}
        int ph = ch >> 1, kc = ch & 1;
        int e = ph ? eb : ea;
        int rowidx = sra;
        if (ph) rowidx = (sra >= TOK) ? (sra - TOK) : (sra + TOK);
        {
            size_t aoff = ((size_t)rowidx) * HID + kc * 64 + half * 32;
            const __nv_bfloat16* ah = g_hh + aoff;
            const __nv_bfloat16* al = g_hl + aoff;
#pragma unroll
            for (int q = 0; q < 4; q++) {
                cp16z(aDstH + q * 16, ah + q * 8, nbA);
                cp16z(aDstL + q * 16, al + q * 8, nbA);
            }
            size_t boff = ((size_t)(e * OUTD + nt * 128 + lr)) * HID + kc * 64 + half * 32;
#pragma unroll
            for (int q = 0; q < 4; q++) {
                cp16(bDstH + q * 16, g_w2h + boff + q * 8);
                cp16(bDstL + q * 16, g_w2l + boff + q * 8);
            }
            CP_COMMIT();
            CP_WAIT0();
        }
        __syncthreads();
#pragma unroll
        for (int ks = 0; ks < 4; ks++) {
            u32 koff = (ks * 16) * 2;
            u32 af[4][4], bhf[4][2], blf[4][2];
#pragma unroll
            for (int mt = 0; mt < 4; mt++) LDSM4(af[mt], aAddrH + mt * 16 * BSTR * 2 + koff);
#pragma unroll
            for (int nn = 0; nn < 4; nn++) {
                LDSM2(bhf[nn], bAddrH + nn * 8 * BSTR * 2 + koff);
                LDSM2(blf[nn], bAddrL + nn * 8 * BSTR * 2 + koff);
            }
#pragma unroll
            for (int mt = 0; mt < 4; mt++)
#pragma unroll
                for (int nn = 0; nn < 4; nn++) {
                    MMA(acc[mt][nn], af[mt], bhf[nn]);
                    MMA(acc[mt][nn], af[mt], blf[nn]);
                }
#pragma unroll
            for (int mt = 0; mt < 4; mt++) LDSM4(af[mt], aAddrL + mt * 16 * BSTR * 2 + koff);
#pragma unroll
            for (int mt = 0; mt < 4; mt++)
#pragma unroll
                for (int nn = 0; nn < 4; nn++)
                    MMA(acc[mt][nn], af[mt], bhf[nn]);
        }
        __syncthreads();
    }

    float* Cs = (float*)sm;
#pragma unroll
    for (int mt = 0; mt < 4; mt++)
#pragma unroll
        for (int nn = 0; nn < 4; nn++) {
            int row = wm * 64 + mt * 16 + (lane >> 2);
            int col = wn * 32 + nn * 8 + (lane & 3) * 2;
            Cs[col * CS_STR + row]           = acc[mt][nn][0];
            Cs[(col + 1) * CS_STR + row]     = acc[mt][nn][1];
            Cs[col * CS_STR + row + 8]       = acc[mt][nn][2];
            Cs[(col + 1) * CS_STR + row + 8] = acc[mt][nn][3];
        }
    __syncthreads();

    const float* ba = b2 + ea * OUTD;
    const float* bb = b2 + eb * OUTD;
    int q = tid & 31, rowgrp = tid >> 5;
    int rA = q >> 1, h4A = (q & 1) * 4;
    int aoffA = rA * 1024 + h0 + h4A;
    int jA = rA * 8 + h4A;
    float bAa[4], bAb[4];
#pragma unroll
    for (int u = 0; u < 4; u++) { bAa[u] = ba[aoffA + u]; bAb[u] = bb[aoffA + u]; }
    int hB = q >> 2, rB4 = (q & 3) * 4;
    int aoffB = h0 * 16 + q * 4;
    int jB[4]; float bBa[4], bBb[4];
#pragma unroll
    for (int u = 0; u < 4; u++) {
        jB[u] = (rB4 + u) * 8 + hB;
        bBa[u] = ba[(rB4 + u) * 1024 + h0 + hB];
        bBb[u] = bb[(rB4 + u) * 1024 + h0 + hB];
    }

#pragma unroll 2
    for (int it = 0; it < 16; it++) {
        int m = it * 8 + rowgrp;
        int bs = sbase[m];
        if (bs < 0) continue;
        float ga = sga[m], gb = sgb[m];
        float4 v; size_t addr;
        if (bs & 1) {
            v.x = Cs[jB[0] * CS_STR + m] + ga * bBa[0] + gb * bBb[0];
            v.y = Cs[jB[1] * CS_STR + m] + ga * bBa[1] + gb * bBb[1];
            v.z = Cs[jB[2] * CS_STR + m] + ga * bBa[2] + gb * bBb[2];
            v.w = Cs[jB[3] * CS_STR + m] + ga * bBa[3] + gb * bBb[3];
            addr = (size_t)BMOFF + (size_t)(bs & ~1) + aoffB;
        } else {
            v.x = Cs[(jA + 0) * CS_STR + m] + ga * bAa[0] + gb * bAb[0];
            v.y = Cs[(jA + 1) * CS_STR + m] + ga * bAa[1] + gb * bAb[1];
            v.z = Cs[(jA + 2) * CS_STR + m] + ga * bAa[2] + gb * bAb[2];
            v.w = Cs[(jA + 3) * CS_STR + m] + ga * bAa[3] + gb * bAb[3];
            addr = (size_t)bs + aoffA;
        }
        *(float4*)(out + addr) = v;
    }
}

// ---------------- K5: aux ----------------
__global__ void k_aux(float* __restrict__ out) {
    if (threadIdx.x == 0 && blockIdx.x == 0) {
        double aux = 0.0;
        for (int s = 0; s < 3; s++) {
            double dot = 0.0;
            for (int e = 0; e < NE; e++) {
                double P = 0.0, L = 0.0;
                for (int b = 0; b < 32; b++) {
                    P += (double)g_psum[b * 3 + s][e];
                    L += (double)g_lsum[b * 3 + s][e];
                }
                dot += P * L;
            }
            double a = 8.0 * dot / (3072.0 * 3072.0) - 1.0;
            if (a > 0.0) aux += a;
        }
        out[AUXOFF] = (float)aux;
    }
}

extern "C" void kernel_launch(void* const* d_in, const int* in_sizes, int n_in,
                              void* d_out, int out_size) {
    const float* z   = (const float*)d_in[0];
    const float* emb = (const float*)d_in[1];
    const float* Wr  = (const float*)d_in[2];
    const float* br  = (const float*)d_in[3];
    const float* W1  = (const float*)d_in[4];
    const float* b1  = (const float*)d_in[5];
    const float* W2  = (const float*)d_in[6];
    const float* b2  = (const float*)d_in[7];
    float* out = (float*)d_out;
    (void)in_sizes; (void)n_in; (void)out_size;

    int smem = 4 * 128 * BSTR * 2;   // 73728 B
    cudaFuncSetAttribute(k_out_pair, cudaFuncAttributeMaxDynamicSharedMemorySize, smem);

    k_w2t<<<dim3(128, NE), 128>>>(W2);                       // also zeroes counters
    k_route<<<96, 512>>>(z, emb, Wr, br);
    k_hidden<<<dim3(TOK / 64, NE, 2), 256>>>(z, emb, W1, b1);
    k_out_pair<<<dim3(MAXT, 128), 256, smem>>>(b2, out);     // 4th launch -> ncu-visible
    k_aux<<<1, 32>>>(out);
}

// round 15
// speedup vs baseline: 1.6483x; 1.0732x over previous
#include <cuda_runtime.h>
#include <cuda_bf16.h>

#define TOK    9216
#define NTOT   288
#define LAT    256
#define DIN    512
#define NE     8
#define HID    128
#define OUTD   16384
#define BMOFF  75497472
#define AUXOFF 150994944
#define CS_STR 131
#define BSTR   72
#define ASZ    18432
#define MAXT   120

typedef unsigned long long ull;
typedef unsigned int u32;

// ---------------- device scratch ----------------
__device__ __align__(16) __nv_bfloat16 g_hh[2 * TOK * HID];
__device__ __align__(16) __nv_bfloat16 g_hl[2 * TOK * HID];
__device__ __align__(16) __nv_bfloat16 g_w2h[NE * OUTD * HID];
__device__ __align__(16) __nv_bfloat16 g_w2l[NE * OUTD * HID];
__device__ int   g_list[2][NE][TOK];
__device__ int   g_cnt[2][NE];
__device__ int   g_plist[64][TOK];    // token | (sa<<14), bucketed by pair a*8+b
__device__ int   g_pcnt[64];
__device__ int   g_tiles[MAXT];
__device__ float g_tokG[2 * TOK];
__device__ float g_psum[96][NE];
__device__ float g_lsum[96][NE];

__device__ __forceinline__ u32 s2u(const void* p) {
    u32 a; asm("{ .reg .u64 t; cvta.to.shared.u64 t, %1; cvt.u32.u64 %0, t; }" : "=r"(a) : "l"(p)); return a;
}
#define LDSM4(f, a) asm volatile("ldmatrix.sync.aligned.m8n8.x4.shared.b16 {%0,%1,%2,%3}, [%4];" \
    : "=r"((f)[0]), "=r"((f)[1]), "=r"((f)[2]), "=r"((f)[3]) : "r"(a))
#define LDSM2(f, a) asm volatile("ldmatrix.sync.aligned.m8n8.x2.shared.b16 {%0,%1}, [%2];" \
    : "=r"((f)[0]), "=r"((f)[1]) : "r"(a))
#define MMA(d, A, Bf) asm volatile( \
    "mma.sync.aligned.m16n8k16.row.col.f32.bf16.bf16.f32 {%0,%1,%2,%3},{%4,%5,%6,%7},{%8,%9},{%0,%1,%2,%3};" \
    : "+f"((d)[0]), "+f"((d)[1]), "+f"((d)[2]), "+f"((d)[3]) \
    : "r"((A)[0]), "r"((A)[1]), "r"((A)[2]), "r"((A)[3]), "r"((Bf)[0]), "r"((Bf)[1]))
#define CP_COMMIT() asm volatile("cp.async.commit_group;" ::: "memory")
#define CP_WAIT0()  asm volatile("cp.async.wait_group 0;" ::: "memory")
#define CP_WAIT1()  asm volatile("cp.async.wait_group 1;" ::: "memory")

__device__ __forceinline__ void cp16(u32 d, const void* s) {
    asm volatile("cp.async.cg.shared.global [%0], [%1], 16;" :: "r"(d), "l"(s));
}
__device__ __forceinline__ void cp16z(u32 d, const void* s, int nb) {
    asm volatile("cp.async.cg.shared.global [%0], [%1], 16, %2;" :: "r"(d), "l"(s), "r"(nb));
}
__device__ __forceinline__ u32 hi2(float a, float b) {
    return (u32)__bfloat16_as_ushort(__float2bfloat16(a)) | ((u32)__bfloat16_as_ushort(__float2bfloat16(b)) << 16);
}
__device__ __forceinline__ u32 lo2(float a, float b) {
    float ra = a - __bfloat162float(__float2bfloat16(a));
    float rb = b - __bfloat162float(__float2bfloat16(b));
    return hi2(ra, rb);
}

// ---------------- K1: W2 transform (+ counter zeroing; runs before k_route) ----------------
__global__ void __launch_bounds__(128) k_w2t(const float* __restrict__ W2) {
    int nt = blockIdx.x, e = blockIdx.y;
    int tid = threadIdx.x;
    if (blockIdx.x == 0 && blockIdx.y == 0) {
        if (tid < 16) ((int*)g_cnt)[tid] = 0;
        if (tid < 64) g_pcnt[tid] = 0;
    }
    __shared__ float s[64][132];
    for (int kp = 0; kp < 2; kp++) {
        for (int task = tid; task < 1024; task += 128) {
            int k = task >> 4, r = task & 15;
            const float* src = W2 + ((size_t)(e * 128 + kp * 64 + k)) * OUTD + r * 1024 + nt * 8;
            float4 v0 = *(const float4*)src, v1 = *(const float4*)(src + 4);
            float* d = &s[k][r * 8];
            *(float4*)d = v0; *(float4*)(d + 4) = v1;
        }
        __syncthreads();
        int j = tid;
        size_t base = ((size_t)(e * OUTD + nt * 128 + j)) * HID + kp * 64;
#pragma unroll
        for (int c = 0; c < 8; c++) {
            u32 wh[4], wl[4];
#pragma unroll
            for (int p = 0; p < 4; p++) {
                float a = s[c * 8 + p * 2][j], b = s[c * 8 + p * 2 + 1][j];
                wh[p] = hi2(a, b); wl[p] = lo2(a, b);
            }
            *(uint4*)&g_w2h[base + c * 8] = make_uint4(wh[0], wh[1], wh[2], wh[3]);
            *(uint4*)&g_w2l[base + c * 8] = make_uint4(wl[0], wl[1], wl[2], wl[3]);
        }
        __syncthreads();
    }
}

// ---------------- K2: routing (512 thr: 16 warps x 6 tokens) ----------------
__global__ void __launch_bounds__(512) k_route(const float* __restrict__ z, const float* __restrict__ emb,
                                               const float* __restrict__ Wr, const float* __restrict__ br) {
    int blk = blockIdx.x, b = blk / 3, s = blk - b * 3;
    int warp = threadIdx.x >> 5, lane = threadIdx.x & 31;
    float accP = 0.f, accL = 0.f;
    for (int it = 0; it < 6; it++) {
        int n = s * 96 + warp * 6 + it;
        int t = b * NTOT + n;
        float lg[8];
#pragma unroll
        for (int e = 0; e < 8; e++) lg[e] = 0.f;
        const float* zr = z + (size_t)t * LAT;
        const float* er = emb + (size_t)n * LAT;
        for (int i = lane; i < DIN; i += 32) {
            float xv = (i < LAT) ? zr[i] : er[i - LAT];
            const float4 w0 = *(const float4*)(Wr + i * 8);
            const float4 w1 = *(const float4*)(Wr + i * 8 + 4);
            lg[0] += xv * w0.x; lg[1] += xv * w0.y; lg[2] += xv * w0.z; lg[3] += xv * w0.w;
            lg[4] += xv * w1.x; lg[5] += xv * w1.y; lg[6] += xv * w1.z; lg[7] += xv * w1.w;
        }
#pragma unroll
        for (int off = 16; off > 0; off >>= 1)
#pragma unroll
            for (int e = 0; e < 8; e++) lg[e] += __shfl_xor_sync(0xffffffffu, lg[e], off);
#pragma unroll
        for (int e = 0; e < 8; e++) lg[e] = (lg[e] + br[e]) * (1.0f / 1.5f);
        int e0 = 0; float v0 = lg[0];
#pragma unroll
        for (int e = 1; e < 8; e++) if (lg[e] > v0) { v0 = lg[e]; e0 = e; }
        int e1 = -1; float v1 = -3.4e38f;
#pragma unroll
        for (int e = 0; e < 8; e++) if (e != e0 && lg[e] > v1) { v1 = lg[e]; e1 = e; }
        float ex = __expf(v1 - v0);
        float g0 = 1.f / (1.f + ex), g1 = ex * g0;
        float den = 0.f, pr[8];
#pragma unroll
        for (int e = 0; e < 8; e++) { pr[e] = __expf(lg[e] - v0); den += pr[e]; }
        float rden = 1.f / den;
        if (lane < 8) {
            accP += pr[lane] * rden;
            accL += (lane == e0 ? g0 : 0.f) + (lane == e1 ? g1 : 0.f);
        }
        if (lane == 0) {
            g_tokG[t] = g0; g_tokG[TOK + t] = g1;
            int p0 = atomicAdd(&g_cnt[0][e0], 1); g_list[0][e0][p0] = t;
            int p1 = atomicAdd(&g_cnt[1][e1], 1); g_list[1][e1][p1] = t;
            int a = min(e0, e1), bb = max(e0, e1);
            int sa = (e0 < e1) ? 0 : 1;
            int pp = a * 8 + bb;
            int pos = atomicAdd(&g_pcnt[pp], 1);
            g_plist[pp][pos] = t | (sa << 14);
        }
    }
    __shared__ float sP[16][8], sL[16][8];
    if (lane < 8) { sP[warp][lane] = accP; sL[warp][lane] = accL; }
    __syncthreads();
    if (threadIdx.x < 8) {
        float p = 0.f, l = 0.f;
        for (int w = 0; w < 16; w++) { p += sP[w][threadIdx.x]; l += sL[w][threadIdx.x]; }
        g_psum[blk][threadIdx.x] = p; g_lsum[blk][threadIdx.x] = l;
    }
}

// ---------------- K3: hidden GEMM + silu + gate -> bf16 hi/lo (+ tile schedule fold) ----------------
__global__ void __launch_bounds__(256) k_hidden(const float* __restrict__ z,
                                                const float* __restrict__ emb,
                                                const float* __restrict__ W1,
                                                const float* __restrict__ b1) {
    int slot = blockIdx.z, e = blockIdx.y;
    int tid = threadIdx.x;
    if (blockIdx.x == 0 && e == 0 && slot == 0 && tid == 255) {   // fold k_sched
        int idx = 0;
        for (int p = 0; p < 64; p++) {
            int c = g_pcnt[p];
            int ntt = (c + 127) >> 7;
            for (int m = 0; m < ntt && idx < MAXT; m++) g_tiles[idx++] = (p << 8) | m;
        }
        while (idx < MAXT) g_tiles[idx++] = -1;
    }
    int cnt = g_cnt[slot][e];
    int m0 = blockIdx.x * 64;
    if (m0 >= cnt) return;
    int rows = min(64, cnt - m0);
    __shared__ __align__(16) float Xs[16][64];
    __shared__ __align__(16) float Ws[16][128];
    __shared__ int stok[64];
    __shared__ float sg[64];
    if (tid < 64) {
        int t = (tid < rows) ? g_list[slot][e][m0 + tid] : -1;
        stok[tid] = t;
        sg[tid] = (t >= 0) ? g_tokG[slot * TOK + t] : 0.f;
    }
    __syncthreads();
    int tx = tid & 15, ty = tid >> 4, j0 = tx * 8, mr = ty * 4;
    float acc[4][8];
#pragma unroll
    for (int a = 0; a < 4; a++)
#pragma unroll
        for (int j = 0; j < 8; j++) acc[a][j] = 0.f;
    const float* W1e = W1 + (size_t)e * DIN * HID;
    int lm = tid >> 2, lq = (tid & 3) * 4, lk = tid >> 4, ln = (tid & 15) * 8;
    for (int k0 = 0; k0 < DIN; k0 += 16) {
        float4 v = make_float4(0.f, 0.f, 0.f, 0.f);
        int t = stok[lm];
        if (t >= 0) {
            int kk = k0 + lq;
            if (kk < LAT) v = *(const float4*)(z + (size_t)t * LAT + kk);
            else          v = *(const float4*)(emb + (size_t)(t % NTOT) * LAT + (kk - LAT));
        }
        const float* src = W1e + (size_t)(k0 + lk) * HID + ln;
        float4 w0 = *(const float4*)src, w1 = *(const float4*)(src + 4);
        __syncthreads();
        Xs[lq][lm] = v.x; Xs[lq + 1][lm] = v.y; Xs[lq + 2][lm] = v.z; Xs[lq + 3][lm] = v.w;
        *(float4*)&Ws[lk][ln] = w0; *(float4*)&Ws[lk][ln + 4] = w1;
        __syncthreads();
#pragma unroll
        for (int kk = 0; kk < 16; kk++) {
            float4 a = *(const float4*)&Xs[kk][mr];
            float4 b0 = *(const float4*)&Ws[kk][j0];
            float4 b1v = *(const float4*)&Ws[kk][j0 + 4];
            float av[4] = {a.x, a.y, a.z, a.w};
            float bv[8] = {b0.x, b0.y, b0.z, b0.w, b1v.x, b1v.y, b1v.z, b1v.w};
#pragma unroll
            for (int mm = 0; mm < 4; mm++)
#pragma unroll
                for (int jj = 0; jj < 8; jj++)
                    acc[mm][jj] = fmaf(av[mm], bv[jj], acc[mm][jj]);
        }
    }
    const float* b1e = b1 + e * HID;
#pragma unroll
    for (int mm = 0; mm < 4; mm++) {
        int m = mr + mm, t = stok[m];
        if (t < 0) continue;
        float g = sg[m], o[8];
#pragma unroll
        for (int jj = 0; jj < 8; jj++) {
            float c = acc[mm][jj] + b1e[j0 + jj];
            o[jj] = c * g / (1.f + __expf(-c));
        }
        size_t base = ((size_t)(slot * TOK + t)) * HID + j0;
        *(uint4*)&g_hh[base] = make_uint4(hi2(o[0], o[1]), hi2(o[2], o[3]), hi2(o[4], o[5]), hi2(o[6], o[7]));
        *(uint4*)&g_hl[base] = make_uint4(lo2(o[0], o[1]), lo2(o[2], o[3]), lo2(o[4], o[5]), lo2(o[6], o[7]));
    }
}

// ---------------- K4: pair-fused output GEMM, B double-buffered cp.async.cg pipeline.
// smem: A{hi,lo} | Bstage0{hi,lo} | Bstage1{hi,lo} = 6 * 18432 = 110592 B
__global__ void __launch_bounds__(256, 2) k_out_pair(const float* __restrict__ b2,
                                                     float* __restrict__ out) {
    int ti = g_tiles[blockIdx.x];
    if (ti < 0) return;
    int pp = ti >> 8, ea = pp >> 3, eb = pp & 7;
    int m0 = (ti & 255) * 128;
    int rows = min(128, g_pcnt[pp] - m0);
    int nt = blockIdx.y, h0 = nt * 8;

    extern __shared__ __align__(16) __nv_bfloat16 sm[];
    u32 smb = s2u(sm);
    __shared__ int   sbase[128];
    __shared__ int   srcrow[128];
    __shared__ float sga[128], sgb[128];

    int tid = threadIdx.x, wid = tid >> 5, lane = tid & 31;
    int wm = wid >> 2, wn = wid & 3;

    if (tid < 128) {
        int base = -1, sr = 0; float ga = 0.f, gb = 0.f;
        if (tid < rows) {
            int tt = g_plist[pp][m0 + tid];
            int t = tt & 16383, sa = (tt >> 14) & 1;
            ga = g_tokG[sa * TOK + t];
            gb = g_tokG[(1 - sa) * TOK + t];
            sr = sa * TOK + t;
            int b = t / NTOT, n = t - b * NTOT;
            int s = n / 96, rem = n - s * 96, l = rem >> 2, jt = rem & 3;
            int chunk = ((b * 3 + s) * 24 + l) * 2 + (jt >> 1);
            base = chunk * OUTD + (jt & 1);
        }
        sbase[tid] = base; srcrow[tid] = sr; sga[tid] = ga; sgb[tid] = gb;
    }
    __syncthreads();

    int lr = tid >> 1, half = tid & 1;
    bool valid = lr < rows;
    int nbA = valid ? 16 : 0;
    int sra = valid ? srcrow[lr] : 0;
    int srb = (sra >= TOK) ? (sra - TOK) : (sra + TOK);

    u32 aDstH = smb + (lr * BSTR + half * 32) * 2;
    u32 aDstL = aDstH + ASZ;
    u32 bDstS = smb + 2 * ASZ + (lr * BSTR + half * 32) * 2;   // + stage*2*ASZ

    // chunk ch: ph = ch>>1 (expert), kc = ch&1 (K half); B stage = ch&1
    #define ISSUE_A(ch) do { \
        int _ph = (ch) >> 1, _kc = (ch) & 1; \
        size_t _ao = (size_t)(_ph ? srb : sra) * HID + _kc * 64 + half * 32; \
        const __nv_bfloat16* _ah = g_hh + _ao; \
        const __nv_bfloat16* _al = g_hl + _ao; \
        cp16z(aDstH,      _ah,      nbA); cp16z(aDstH + 16, _ah + 8,  nbA); \
        cp16z(aDstH + 32, _ah + 16, nbA); cp16z(aDstH + 48, _ah + 24, nbA); \
        cp16z(aDstL,      _al,      nbA); cp16z(aDstL + 16, _al + 8,  nbA); \
        cp16z(aDstL + 32, _al + 16, nbA); cp16z(aDstL + 48, _al + 24, nbA); \
    } while (0)
    #define ISSUE_B(ch) do { \
        int _ph = (ch) >> 1, _kc = (ch) & 1; \
        int _e = _ph ? eb : ea; \
        size_t _bo = ((size_t)(_e * OUTD + nt * 128 + lr)) * HID + _kc * 64 + half * 32; \
        u32 _d = bDstS + ((ch) & 1) * 2 * ASZ; \
        const __nv_bfloat16* _bh = g_w2h + _bo; \
        const __nv_bfloat16* _bl = g_w2l + _bo; \
        cp16(_d,            _bh);      cp16(_d + 16,       _bh + 8); \
        cp16(_d + 32,       _bh + 16); cp16(_d + 48,       _bh + 24); \
        cp16(_d + ASZ,      _bl);      cp16(_d + ASZ + 16, _bl + 8); \
        cp16(_d + ASZ + 32, _bl + 16); cp16(_d + ASZ + 48, _bl + 24); \
    } while (0)

    // prologue: A0+B0 (group), B1 (group); wait for A0+B0
    ISSUE_A(0); ISSUE_B(0); CP_COMMIT();
    ISSUE_B(1); CP_COMMIT();
    CP_WAIT1();
    __syncthreads();

    float acc[4][4][4];
#pragma unroll
    for (int i = 0; i < 4; i++)
#pragma unroll
        for (int j = 0; j < 4; j++)
#pragma unroll
            for (int p = 0; p < 4; p++) acc[i][j][p] = 0.f;

    u32 aRow = wm * 64 + (lane & 7) + ((lane >> 3) & 1) * 8;
    u32 aKof = (lane >> 4) * 8;
    int ll = lane & 15;
    u32 bRow = wn * 32 + (ll & 7);
    u32 bKof = ((ll >> 3) & 1) * 8;
    u32 aAddrH = smb + (aRow * BSTR + aKof) * 2;
    u32 aAddrL = aAddrH + ASZ;
    u32 bAddrOff = (bRow * BSTR + bKof) * 2;

    for (int ch = 0; ch < 4; ch++) {
        u32 bAddrH = smb + (2 + 2 * (ch & 1)) * ASZ + bAddrOff;
        u32 bAddrL = bAddrH + ASZ;
#pragma unroll
        for (int ks = 0; ks < 4; ks++) {
            u32 koff = (ks * 16) * 2;
            u32 af[4][4], bhf[4][2], blf[4][2];
#pragma unroll
            for (int mt = 0; mt < 4; mt++) LDSM4(af[mt], aAddrH + mt * 16 * BSTR * 2 + koff);
#pragma unroll
            for (int nn = 0; nn < 4; nn++) {
                LDSM2(bhf[nn], bAddrH + nn * 8 * BSTR * 2 + koff);
                LDSM2(blf[nn], bAddrL + nn * 8 * BSTR * 2 + koff);
            }
#pragma unroll
            for (int mt = 0; mt < 4; mt++)
#pragma unroll
                for (int nn = 0; nn < 4; nn++) {
                    MMA(acc[mt][nn], af[mt], bhf[nn]);
                    MMA(acc[mt][nn], af[mt], blf[nn]);
                }
#pragma unroll
            for (int mt = 0; mt < 4; mt++) LDSM4(af[mt], aAddrL + mt * 16 * BSTR * 2 + koff);
#pragma unroll
            for (int mt = 0; mt < 4; mt++)
#pragma unroll
                for (int nn = 0; nn < 4; nn++)
                    MMA(acc[mt][nn], af[mt], bhf[nn]);
        }
        __syncthreads();               // A + B-stage readers done
        if (ch < 3) {
            ISSUE_A(ch + 1); CP_COMMIT();
            if (ch < 2) { ISSUE_B(ch + 2); CP_COMMIT(); CP_WAIT1(); }
            else        { CP_WAIT0(); }
            __syncthreads();
        }
    }

    // acc -> Cs [col][m]
    float* Cs = (float*)sm;
#pragma unroll
    for (int mt = 0; mt < 4; mt++)
#pragma unroll
        for (int nn = 0; nn < 4; nn++) {
            int row = wm * 64 + mt * 16 + (lane >> 2);
            int col = wn * 32 + nn * 8 + (lane & 3) * 2;
            Cs[col * CS_STR + row]           = acc[mt][nn][0];
            Cs[(col + 1) * CS_STR + row]     = acc[mt][nn][1];
            Cs[col * CS_STR + row + 8]       = acc[mt][nn][2];
            Cs[(col + 1) * CS_STR + row + 8] = acc[mt][nn][3];
        }
    __syncthreads();

    // vectorized single-write epilogue
    const float* ba = b2 + ea * OUTD;
    const float* bb = b2 + eb * OUTD;
    int q = tid & 31, rowgrp = tid >> 5;
    int rA = q >> 1, h4A = (q & 1) * 4;
    int aoffA = rA * 1024 + h0 + h4A;
    int jA = rA * 8 + h4A;
    float bAa[4], bAb[4];
#pragma unroll
    for (int u = 0; u < 4; u++) { bAa[u] = ba[aoffA + u]; bAb[u] = bb[aoffA + u]; }
    int hB = q >> 2, rB4 = (q & 3) * 4;
    int aoffB = h0 * 16 + q * 4;
    int jB[4]; float bBa[4], bBb[4];
#pragma unroll
    for (int u = 0; u < 4; u++) {
        jB[u] = (rB4 + u) * 8 + hB;
        bBa[u] = ba[(rB4 + u) * 1024 + h0 + hB];
        bBb[u] = bb[(rB4 + u) * 1024 + h0 + hB];
    }

#pragma unroll 2
    for (int it = 0; it < 16; it++) {
        int m = it * 8 + rowgrp;
        int bs = sbase[m];
        if (bs < 0) continue;
        float ga = sga[m], gb = sgb[m];
        float4 v; size_t addr;
        if (bs & 1) {
            v.x = Cs[jB[0] * CS_STR + m] + ga * bBa[0] + gb * bBb[0];
            v.y = Cs[jB[1] * CS_STR + m] + ga * bBa[1] + gb * bBb[1];
            v.z = Cs[jB[2] * CS_STR + m] + ga * bBa[2] + gb * bBb[2];
            v.w = Cs[jB[3] * CS_STR + m] + ga * bBa[3] + gb * bBb[3];
            addr = (size_t)BMOFF + (size_t)(bs & ~1) + aoffB;
        } else {
            v.x = Cs[(jA + 0) * CS_STR + m] + ga * bAa[0] + gb * bAb[0];
            v.y = Cs[(jA + 1) * CS_STR + m] + ga * bAa[1] + gb * bAb[1];
            v.z = Cs[(jA + 2) * CS_STR + m] + ga * bAa[2] + gb * bAb[2];
            v.w = Cs[(jA + 3) * CS_STR + m] + ga * bAa[3] + gb * bAb[3];
            addr = (size_t)bs + aoffA;
        }
        *(float4*)(out + addr) = v;
    }
}

// ---------------- K5: aux ----------------
__global__ void k_aux(float* __restrict__ out) {
    if (threadIdx.x == 0 && blockIdx.x == 0) {
        double aux = 0.0;
        for (int s = 0; s < 3; s++) {
            double dot = 0.0;
            for (int e = 0; e < NE; e++) {
                double P = 0.0, L = 0.0;
                for (int b = 0; b < 32; b++) {
                    P += (double)g_psum[b * 3 + s][e];
                    L += (double)g_lsum[b * 3 + s][e];
                }
                dot += P * L;
            }
            double a = 8.0 * dot / (3072.0 * 3072.0) - 1.0;
            if (a > 0.0) aux += a;
        }
        out[AUXOFF] = (float)aux;
    }
}

extern "C" void kernel_launch(void* const* d_in, const int* in_sizes, int n_in,
                              void* d_out, int out_size) {
    const float* z   = (const float*)d_in[0];
    const float* emb = (const float*)d_in[1];
    const float* Wr  = (const float*)d_in[2];
    const float* br  = (const float*)d_in[3];
    const float* W1  = (const float*)d_in[4];
    const float* b1  = (const float*)d_in[5];
    const float* W2  = (const float*)d_in[6];
    const float* b2  = (const float*)d_in[7];
    float* out = (float*)d_out;
    (void)in_sizes; (void)n_in; (void)out_size;

    int smem = 6 * ASZ;   // 110592 B
    cudaFuncSetAttribute(k_out_pair, cudaFuncAttributeMaxDynamicSharedMemorySize, smem);

    k_w2t<<<dim3(128, NE), 128>>>(W2);                       // also zeroes counters
    k_route<<<96, 512>>>(z, emb, Wr, br);
    k_hidden<<<dim3(TOK / 64, NE, 2), 256>>>(z, emb, W1, b1);   // also builds g_tiles
    k_out_pair<<<dim3(MAXT, 128), 256, smem>>>(b2, out);     // 4th launch -> ncu-visible
    k_aux<<<1, 32>>>(out);
}

// round 17
// speedup vs baseline: 2.8017x; 1.6997x over previous
#include <cuda_runtime.h>
#include <cuda_bf16.h>
#include <cuda_fp16.h>

#define TOK    9216
#define NTOT   288
#define LAT    256
#define DIN    512
#define NE     8
#define HID    128
#define OUTD   16384
#define BMOFF  75497472
#define AUXOFF 150994944
#define CS_STR 131
#define BSTR   72
#define ASZ    18432
#define MAXT   120

typedef unsigned long long ull;
typedef unsigned int u32;

// ---------------- device scratch ----------------
__device__ __align__(16) __half g_h[2 * TOK * HID];        // fp16 gate-folded hidden
__device__ __align__(16) __half g_w2[NE * OUTD * HID];     // fp16 permuted K-major W2^T
__device__ int   g_list[2][NE][TOK];
__device__ int   g_cnt[2][NE];
__device__ int   g_plist[64][TOK];    // token | (sa<<14), bucketed by pair a*8+b
__device__ int   g_pcnt[64];
__device__ int   g_tiles[MAXT];
__device__ float g_tokG[2 * TOK];
__device__ float g_psum[96][NE];
__device__ float g_lsum[96][NE];

__device__ __forceinline__ u32 s2u(const void* p) {
    u32 a; asm("{ .reg .u64 t; cvta.to.shared.u64 t, %1; cvt.u32.u64 %0, t; }" : "=r"(a) : "l"(p)); return a;
}
#define LDSM4(f, a) asm volatile("ldmatrix.sync.aligned.m8n8.x4.shared.b16 {%0,%1,%2,%3}, [%4];" \
    : "=r"((f)[0]), "=r"((f)[1]), "=r"((f)[2]), "=r"((f)[3]) : "r"(a))
#define LDSM2(f, a) asm volatile("ldmatrix.sync.aligned.m8n8.x2.shared.b16 {%0,%1}, [%2];" \
    : "=r"((f)[0]), "=r"((f)[1]) : "r"(a))
#define MMA(d, A, Bf) asm volatile( \
    "mma.sync.aligned.m16n8k16.row.col.f32.f16.f16.f32 {%0,%1,%2,%3},{%4,%5,%6,%7},{%8,%9},{%0,%1,%2,%3};" \
    : "+f"((d)[0]), "+f"((d)[1]), "+f"((d)[2]), "+f"((d)[3]) \
    : "r"((A)[0]), "r"((A)[1]), "r"((A)[2]), "r"((A)[3]), "r"((Bf)[0]), "r"((Bf)[1]))
#define CP_COMMIT() asm volatile("cp.async.commit_group;" ::: "memory")
#define CP_WAIT0()  asm volatile("cp.async.wait_group 0;" ::: "memory")
#define CP_WAIT1()  asm volatile("cp.async.wait_group 1;" ::: "memory")

__device__ __forceinline__ void cp16(u32 d, const void* s) {
    asm volatile("cp.async.cg.shared.global [%0], [%1], 16;" :: "r"(d), "l"(s));
}
__device__ __forceinline__ void cp16z(u32 d, const void* s, int nb) {
    asm volatile("cp.async.cg.shared.global [%0], [%1], 16, %2;" :: "r"(d), "l"(s), "r"(nb));
}
__device__ __forceinline__ u32 h2(float a, float b) {
    __half2 v = __floats2half2_rn(a, b);
    return *(u32*)&v;
}

// ---------------- K1: W2 transform -> fp16 permuted K-major (+ counter zeroing) ----------------
__global__ void __launch_bounds__(128) k_w2t(const float* __restrict__ W2) {
    int nt = blockIdx.x, e = blockIdx.y;
    int tid = threadIdx.x;
    if (blockIdx.x == 0 && blockIdx.y == 0) {
        if (tid < 16) ((int*)g_cnt)[tid] = 0;
        if (tid < 64) g_pcnt[tid] = 0;
    }
    __shared__ float s[64][132];
    for (int kp = 0; kp < 2; kp++) {
        for (int task = tid; task < 1024; task += 128) {
            int k = task >> 4, r = task & 15;
            const float* src = W2 + ((size_t)(e * 128 + kp * 64 + k)) * OUTD + r * 1024 + nt * 8;
            float4 v0 = *(const float4*)src, v1 = *(const float4*)(src + 4);
            float* d = &s[k][r * 8];
            *(float4*)d = v0; *(float4*)(d + 4) = v1;
        }
        __syncthreads();
        int j = tid;
        size_t base = ((size_t)(e * OUTD + nt * 128 + j)) * HID + kp * 64;
#pragma unroll
        for (int q = 0; q < 8; q++) {
            uint4 w = make_uint4(h2(s[q * 8 + 0][j], s[q * 8 + 1][j]),
                                 h2(s[q * 8 + 2][j], s[q * 8 + 3][j]),
                                 h2(s[q * 8 + 4][j], s[q * 8 + 5][j]),
                                 h2(s[q * 8 + 6][j], s[q * 8 + 7][j]));
            *(uint4*)&g_w2[base + q * 8] = w;
        }
        __syncthreads();
    }
}

// ---------------- K2: routing (512 thr: 16 warps x 6 tokens) ----------------
__global__ void __launch_bounds__(512) k_route(const float* __restrict__ z, const float* __restrict__ emb,
                                               const float* __restrict__ Wr, const float* __restrict__ br) {
    int blk = blockIdx.x, b = blk / 3, s = blk - b * 3;
    int warp = threadIdx.x >> 5, lane = threadIdx.x & 31;
    float accP = 0.f, accL = 0.f;
    for (int it = 0; it < 6; it++) {
        int n = s * 96 + warp * 6 + it;
        int t = b * NTOT + n;
        float lg[8];
#pragma unroll
        for (int e = 0; e < 8; e++) lg[e] = 0.f;
        const float* zr = z + (size_t)t * LAT;
        const float* er = emb + (size_t)n * LAT;
        for (int i = lane; i < DIN; i += 32) {
            float xv = (i < LAT) ? zr[i] : er[i - LAT];
            const float4 w0 = *(const float4*)(Wr + i * 8);
            const float4 w1 = *(const float4*)(Wr + i * 8 + 4);
            lg[0] += xv * w0.x; lg[1] += xv * w0.y; lg[2] += xv * w0.z; lg[3] += xv * w0.w;
            lg[4] += xv * w1.x; lg[5] += xv * w1.y; lg[6] += xv * w1.z; lg[7] += xv * w1.w;
        }
#pragma unroll
        for (int off = 16; off > 0; off >>= 1)
#pragma unroll
            for (int e = 0; e < 8; e++) lg[e] += __shfl_xor_sync(0xffffffffu, lg[e], off);
#pragma unroll
        for (int e = 0; e < 8; e++) lg[e] = (lg[e] + br[e]) * (1.0f / 1.5f);
        int e0 = 0; float v0 = lg[0];
#pragma unroll
        for (int e = 1; e < 8; e++) if (lg[e] > v0) { v0 = lg[e]; e0 = e; }
        int e1 = -1; float v1 = -3.4e38f;
#pragma unroll
        for (int e = 0; e < 8; e++) if (e != e0 && lg[e] > v1) { v1 = lg[e]; e1 = e; }
        float ex = __expf(v1 - v0);
        float g0 = 1.f / (1.f + ex), g1 = ex * g0;
        float den = 0.f, pr[8];
#pragma unroll
        for (int e = 0; e < 8; e++) { pr[e] = __expf(lg[e] - v0); den += pr[e]; }
        float rden = 1.f / den;
        if (lane < 8) {
            accP += pr[lane] * rden;
            accL += (lane == e0 ? g0 : 0.f) + (lane == e1 ? g1 : 0.f);
        }
        if (lane == 0) {
            g_tokG[t] = g0; g_tokG[TOK + t] = g1;
            int p0 = atomicAdd(&g_cnt[0][e0], 1); g_list[0][e0][p0] = t;
            int p1 = atomicAdd(&g_cnt[1][e1], 1); g_list[1][e1][p1] = t;
            int a = min(e0, e1), bb = max(e0, e1);
            int sa = (e0 < e1) ? 0 : 1;
            int pp = a * 8 + bb;
            int pos = atomicAdd(&g_pcnt[pp], 1);
            g_plist[pp][pos] = t | (sa << 14);
        }
    }
    __shared__ float sP[16][8], sL[16][8];
    if (lane < 8) { sP[warp][lane] = accP; sL[warp][lane] = accL; }
    __syncthreads();
    if (threadIdx.x < 8) {
        float p = 0.f, l = 0.f;
        for (int w = 0; w < 16; w++) { p += sP[w][threadIdx.x]; l += sL[w][threadIdx.x]; }
        g_psum[blk][threadIdx.x] = p; g_lsum[blk][threadIdx.x] = l;
    }
}

// ---------------- K3: hidden GEMM + silu + gate -> fp16 (+ tile schedule fold) ----------------
__global__ void __launch_bounds__(256) k_hidden(const float* __restrict__ z,
                                                const float* __restrict__ emb,
                                                const float* __restrict__ W1,
                                                const float* __restrict__ b1) {
    int slot = blockIdx.z, e = blockIdx.y;
    int tid = threadIdx.x;
    if (blockIdx.x == 0 && e == 0 && slot == 0 && tid == 255) {   // fold k_sched
        int idx = 0;
        for (int p = 0; p < 64; p++) {
            int c = g_pcnt[p];
            int ntt = (c + 127) >> 7;
            for (int m = 0; m < ntt && idx < MAXT; m++) g_tiles[idx++] = (p << 8) | m;
        }
        while (idx < MAXT) g_tiles[idx++] = -1;
    }
    int cnt = g_cnt[slot][e];
    int m0 = blockIdx.x * 64;
    if (m0 >= cnt) return;
    int rows = min(64, cnt - m0);
    __shared__ __align__(16) float Xs[16][64];
    __shared__ __align__(16) float Ws[16][128];
    __shared__ int stok[64];
    __shared__ float sg[64];
    if (tid < 64) {
        int t = (tid < rows) ? g_list[slot][e][m0 + tid] : -1;
        stok[tid] = t;
        sg[tid] = (t >= 0) ? g_tokG[slot * TOK + t] : 0.f;
    }
    __syncthreads();
    int tx = tid & 15, ty = tid >> 4, j0 = tx * 8, mr = ty * 4;
    float acc[4][8];
#pragma unroll
    for (int a = 0; a < 4; a++)
#pragma unroll
        for (int j = 0; j < 8; j++) acc[a][j] = 0.f;
    const float* W1e = W1 + (size_t)e * DIN * HID;
    int lm = tid >> 2, lq = (tid & 3) * 4, lk = tid >> 4, ln = (tid & 15) * 8;
    for (int k0 = 0; k0 < DIN; k0 += 16) {
        float4 v = make_float4(0.f, 0.f, 0.f, 0.f);
        int t = stok[lm];
        if (t >= 0) {
            int kk = k0 + lq;
            if (kk < LAT) v = *(const float4*)(z + (size_t)t * LAT + kk);
            else          v = *(const float4*)(emb + (size_t)(t % NTOT) * LAT + (kk - LAT));
        }
        const float* src = W1e + (size_t)(k0 + lk) * HID + ln;
        float4 w0 = *(const float4*)src, w1 = *(const float4*)(src + 4);
        __syncthreads();
        Xs[lq][lm] = v.x; Xs[lq + 1][lm] = v.y; Xs[lq + 2][lm] = v.z; Xs[lq + 3][lm] = v.w;
        *(float4*)&Ws[lk][ln] = w0; *(float4*)&Ws[lk][ln + 4] = w1;
        __syncthreads();
#pragma unroll
        for (int kk = 0; kk < 16; kk++) {
            float4 a = *(const float4*)&Xs[kk][mr];
            float4 b0 = *(const float4*)&Ws[kk][j0];
            float4 b1v = *(const float4*)&Ws[kk][j0 + 4];
            float av[4] = {a.x, a.y, a.z, a.w};
            float bv[8] = {b0.x, b0.y, b0.z, b0.w, b1v.x, b1v.y, b1v.z, b1v.w};
#pragma unroll
            for (int mm = 0; mm < 4; mm++)
#pragma unroll
                for (int jj = 0; jj < 8; jj++)
                    acc[mm][jj] = fmaf(av[mm], bv[jj], acc[mm][jj]);
        }
    }
    const float* b1e = b1 + e * HID;
#pragma unroll
    for (int mm = 0; mm < 4; mm++) {
        int m = mr + mm, t = stok[m];
        if (t < 0) continue;
        float g = sg[m], o[8];
#pragma unroll
        for (int jj = 0; jj < 8; jj++) {
            float c = acc[mm][jj] + b1e[j0 + jj];
            o[jj] = c * g / (1.f + __expf(-c));
        }
        size_t base = ((size_t)(slot * TOK + t)) * HID + j0;
        *(uint4*)&g_h[base] = make_uint4(h2(o[0], o[1]), h2(o[2], o[3]),
                                         h2(o[4], o[5]), h2(o[6], o[7]));
    }
}

// ---------------- K4: pair-fused fp16 output GEMM, 3-stage A+B cp.async pipeline.
// smem per stage: A(18432) + B(18432); 3 stages = 110592 B. Cs reuses the region.
__global__ void __launch_bounds__(256, 2) k_out_pair(const float* __restrict__ b2,
                                                     float* __restrict__ out) {
    int ti = g_tiles[blockIdx.x];
    if (ti < 0) return;
    int pp = ti >> 8, ea = pp >> 3, eb = pp & 7;
    int m0 = (ti & 255) * 128;
    int rows = min(128, g_pcnt[pp] - m0);
    int nt = blockIdx.y, h0 = nt * 8;

    extern __shared__ __align__(16) __half sm[];
    u32 smb = s2u(sm);
    __shared__ int   sbase[128];
    __shared__ int   srcrow[128];
    __shared__ float sga[128], sgb[128];

    int tid = threadIdx.x, wid = tid >> 5, lane = tid & 31;
    int wm = wid >> 2, wn = wid & 3;

    if (tid < 128) {
        int base = -1, sr = 0; float ga = 0.f, gb = 0.f;
        if (tid < rows) {
            int tt = g_plist[pp][m0 + tid];
            int t = tt & 16383, sa = (tt >> 14) & 1;
            ga = g_tokG[sa * TOK + t];
            gb = g_tokG[(1 - sa) * TOK + t];
            sr = sa * TOK + t;
            int b = t / NTOT, n = t - b * NTOT;
            int s = n / 96, rem = n - s * 96, l = rem >> 2, jt = rem & 3;
            int chunk = ((b * 3 + s) * 24 + l) * 2 + (jt >> 1);
            base = chunk * OUTD + (jt & 1);
        }
        sbase[tid] = base; srcrow[tid] = sr; sga[tid] = ga; sgb[tid] = gb;
    }
    __syncthreads();

    int lr = tid >> 1, half = tid & 1;
    bool valid = lr < rows;
    int nbA = valid ? 16 : 0;
    int sra = valid ? srcrow[lr] : 0;
    int srb = (sra >= TOK) ? (sra - TOK) : (sra + TOK);
    u32 fillOff = (u32)(lr * BSTR + half * 32) * 2;

    // chunk ch: ph = ch>>1 (expert), kc = ch&1 (K half); stage = ch % 3
    #define ISSUE(ch, st) do { \
        int _ph = (ch) >> 1, _kc = (ch) & 1; \
        u32 _s = smb + (u32)(st) * 2 * ASZ + fillOff; \
        size_t _ao = (size_t)(_ph ? srb : sra) * HID + _kc * 64 + half * 32; \
        const __half* _a = g_h + _ao; \
        cp16z(_s,      _a,      nbA); cp16z(_s + 16, _a + 8,  nbA); \
        cp16z(_s + 32, _a + 16, nbA); cp16z(_s + 48, _a + 24, nbA); \
        int _e = _ph ? eb : ea; \
        size_t _bo = ((size_t)(_e * OUTD + nt * 128 + lr)) * HID + _kc * 64 + half * 32; \
        const __half* _b = g_w2 + _bo; \
        u32 _d = _s + ASZ; \
        cp16(_d,      _b);      cp16(_d + 16, _b + 8); \
        cp16(_d + 32, _b + 16); cp16(_d + 48, _b + 24); \
    } while (0)

    ISSUE(0, 0); CP_COMMIT();
    ISSUE(1, 1); CP_COMMIT();
    CP_WAIT1();
    __syncthreads();

    float acc[4][4][4];
#pragma unroll
    for (int i = 0; i < 4; i++)
#pragma unroll
        for (int j = 0; j < 4; j++)
#pragma unroll
            for (int p = 0; p < 4; p++) acc[i][j][p] = 0.f;

    u32 aRow = wm * 64 + (lane & 7) + ((lane >> 3) & 1) * 8;
    u32 aKof = (lane >> 4) * 8;
    int ll = lane & 15;
    u32 bRow = wn * 32 + (ll & 7);
    u32 bKof = ((ll >> 3) & 1) * 8;
    u32 aOff = (aRow * BSTR + aKof) * 2;
    u32 bOff = (bRow * BSTR + bKof) * 2 + ASZ;

    for (int ch = 0; ch < 4; ch++) {
        u32 sb = smb + (u32)(ch % 3) * 2 * ASZ;
        u32 aAddr = sb + aOff;
        u32 bAddr = sb + bOff;
#pragma unroll
        for (int ks = 0; ks < 4; ks++) {
            u32 koff = (ks * 16) * 2;
            u32 af[4][4], bf[4][2];
#pragma unroll
            for (int mt = 0; mt < 4; mt++) LDSM4(af[mt], aAddr + mt * 16 * BSTR * 2 + koff);
#pragma unroll
            for (int nn = 0; nn < 4; nn++) LDSM2(bf[nn], bAddr + nn * 8 * BSTR * 2 + koff);
#pragma unroll
            for (int mt = 0; mt < 4; mt++)
#pragma unroll
                for (int nn = 0; nn < 4; nn++)
                    MMA(acc[mt][nn], af[mt], bf[nn]);
        }
        if (ch < 2) { ISSUE(ch + 2, (ch + 2) % 3); CP_COMMIT(); }
        if (ch < 3) { if (ch < 2) CP_WAIT1(); else CP_WAIT0(); }
        __syncthreads();
    }

    // acc -> Cs [col][m]
    float* Cs = (float*)sm;
#pragma unroll
    for (int mt = 0; mt < 4; mt++)
#pragma unroll
        for (int nn = 0; nn < 4; nn++) {
            int row = wm * 64 + mt * 16 + (lane >> 2);
            int col = wn * 32 + nn * 8 + (lane & 3) * 2;
            Cs[col * CS_STR + row]           = acc[mt][nn][0];
            Cs[(col + 1) * CS_STR + row]     = acc[mt][nn][1];
            Cs[col * CS_STR + row + 8]       = acc[mt][nn][2];
            Cs[(col + 1) * CS_STR + row + 8] = acc[mt][nn][3];
        }
    __syncthreads();

    // vectorized single-write epilogue
    const float* ba = b2 + ea * OUTD;
    const float* bb = b2 + eb * OUTD;
    int q = tid & 31, rowgrp = tid >> 5;
    int rA = q >> 1, h4A = (q & 1) * 4;
    int aoffA = rA * 1024 + h0 + h4A;
    int jA = rA * 8 + h4A;
    float bAa[4], bAb[4];
#pragma unroll
    for (int u = 0; u < 4; u++) { bAa[u] = ba[aoffA + u]; bAb[u] = bb[aoffA + u]; }
    int hB = q >> 2, rB4 = (q & 3) * 4;
    int aoffB = h0 * 16 + q * 4;
    int jB[4]; float bBa[4], bBb[4];
#pragma unroll
    for (int u = 0; u < 4; u++) {
        jB[u] = (rB4 + u) * 8 + hB;
        bBa[u] = ba[(rB4 + u) * 1024 + h0 + hB];
        bBb[u] = bb[(rB4 + u) * 1024 + h0 + hB];
    }

#pragma unroll 2
    for (int it = 0; it < 16; it++) {
        int m = it * 8 + rowgrp;
        int bs = sbase[m];
        if (bs < 0) continue;
        float ga = sga[m], gb = sgb[m];
        float4 v; size_t addr;
        if (bs & 1) {
            v.x = Cs[jB[0] * CS_STR + m] + ga * bBa[0] + gb * bBb[0];
            v.y = Cs[jB[1] * CS_STR + m] + ga * bBa[1] + gb * bBb[1];
            v.z = Cs[jB[2] * CS_STR + m] + ga * bBa[2] + gb * bBb[2];
            v.w = Cs[jB[3] * CS_STR + m] + ga * bBa[3] + gb * bBb[3];
            addr = (size_t)BMOFF + (size_t)(bs & ~1) + aoffB;
        } else {
            v.x = Cs[(jA + 0) * CS_STR + m] + ga * bAa[0] + gb * bAb[0];
            v.y = Cs[(jA + 1) * CS_STR + m] + ga * bAa[1] + gb * bAb[1];
            v.z = Cs[(jA + 2) * CS_STR + m] + ga * bAa[2] + gb * bAb[2];
            v.w = Cs[(jA + 3) * CS_STR + m] + ga * bAa[3] + gb * bAb[3];
            addr = (size_t)bs + aoffA;
        }
        *(float4*)(out + addr) = v;
    }
}

// ---------------- K5: aux (parallel deterministic partials) ----------------
__global__ void k_aux(float* __restrict__ out) {
    __shared__ double sP[24], sL[24];
    int tid = threadIdx.x;
    if (tid < 24) {
        int s = tid >> 3, e = tid & 7;
        double P = 0.0, L = 0.0;
        for (int b = 0; b < 32; b++) {
            P += (double)g_psum[b * 3 + s][e];
            L += (double)g_lsum[b * 3 + s][e];
        }
        sP[tid] = P; sL[tid] = L;
    }
    __syncthreads();
    if (tid == 0) {
        double aux = 0.0;
        for (int s = 0; s < 3; s++) {
            double dot = 0.0;
            for (int e = 0; e < NE; e++) dot += sP[s * 8 + e] * sL[s * 8 + e];
            double a = 8.0 * dot / (3072.0 * 3072.0) - 1.0;
            if (a > 0.0) aux += a;
        }
        out[AUXOFF] = (float)aux;
    }
}

extern "C" void kernel_launch(void* const* d_in, const int* in_sizes, int n_in,
                              void* d_out, int out_size) {
    const float* z   = (const float*)d_in[0];
    const float* emb = (const float*)d_in[1];
    const float* Wr  = (const float*)d_in[2];
    const float* br  = (const float*)d_in[3];
    const float* W1  = (const float*)d_in[4];
    const float* b1  = (const float*)d_in[5];
    const float* W2  = (const float*)d_in[6];
    const float* b2  = (const float*)d_in[7];
    float* out = (float*)d_out;
    (void)in_sizes; (void)n_in; (void)out_size;

    int smem = 6 * ASZ;   // 110592 B (3 stages x (A+B)); Cs fits inside
    cudaFuncSetAttribute(k_out_pair, cudaFuncAttributeMaxDynamicSharedMemorySize, smem);

    k_w2t<<<dim3(128, NE), 128>>>(W2);                       // also zeroes counters
    k_route<<<96, 512>>>(z, emb, Wr, br);
    k_hidden<<<dim3(TOK / 64, NE, 2), 256>>>(z, emb, W1, b1);   // also builds g_tiles
    k_out_pair<<<dim3(MAXT, 128), 256, smem>>>(b2, out);     // 4th launch -> ncu-visible
    k_aux<<<1, 32>>>(out);
}